// round 13
// baseline (speedup 1.0000x reference)
#include <cuda_runtime.h>
#include <math.h>

// Problem constants
#define B_    32
#define C_    256
#define L_    8192
#define H_    16
#define ROWS  (B_ * C_)          // 8192
#define L4    (L_ / 4)           // 2048 float4 per row
#define ITER  8
#define TPB   256

// 1-row tasks (R7 geometry — proven 494MB traffic).
// mean-stream: per batch [256 means, 1 excite] = 257*32 = 8224
// scale-stream: 8192.
#define NM    (B_ * (C_ + 1))    // 8224
#define NS    ROWS               // 8192
#define NTASKS (NM + NS)         // 16416 (even — pair grab safe)
#define LEAD  1200               // rescaled for 2-slot grab slack (~1776)
#define ALT_END (LEAD + 2 * (NM - LEAD))   // 15248
#define P_BLOCKS 888

// Scratch (allocation-free rule: __device__ globals)
__device__ float d_y[ROWS];
__device__ float d_g[ROWS];
__device__ int   g_task;
__device__ int   g_cnt[B_];
__device__ int   g_flag[B_];

// ---------------------------------------------------------------------------
__global__ void se_init() {
    const int t = threadIdx.x;
    if (t == 0) g_task = 0;
    if (t < B_) { g_cnt[t] = 0; g_flag[t] = 0; }
}

// ---------------------------------------------------------------------------
// Persistent worker. Dynamic IN-ORDER queue, TWO positions per grab:
// halves dispatch overhead while keeping the 32KB/slot footprint that makes
// the L2 reuse window fit (R10/R11 showed 64KB/slot thrashes). Grab happens
// only after the previous pair is fully processed (no prefetch — R8 lesson).
// ---------------------------------------------------------------------------
__global__ __launch_bounds__(TPB, 6) void se_persist(const float4* __restrict__ x,
                                                     float4* __restrict__ out,
                                                     const float* __restrict__ W1,
                                                     const float* __restrict__ W2) {
    __shared__ int   s_task;
    __shared__ float warp_sums[8];
    __shared__ float ys[C_];
    __shared__ float hs[H_];

    const int t    = threadIdx.x;
    const int lane = t & 31;
    const int wid  = t >> 5;

    for (;;) {
        if (t == 0) s_task = atomicAdd(&g_task, 2);
        __syncthreads();
        const int base = s_task;
        if (base >= NTASKS) return;

        #pragma unroll 1
        for (int q = 0; q < 2; ++q) {
            const int task = base + q;
            if (task >= NTASKS) break;

            // ---- queue position -> (stream, index) ----
            int mean_idx = -1, scale_idx = -1;
            if (task < LEAD) {
                mean_idx = task;
            } else if (task < ALT_END) {
                const int j = task - LEAD;
                if (j & 1) mean_idx = LEAD + (j >> 1);
                else       scale_idx = j >> 1;
            } else {
                scale_idx = (NM - LEAD) + (task - ALT_END);
            }

            if (mean_idx >= 0) {
                const int b = mean_idx / (C_ + 1);
                const int r = mean_idx - b * (C_ + 1);
                if (r < C_) {
                    // ---- MEAN of row (b, r): default policy -> L2 resident
                    const int row = b * C_ + r;
                    const float4* __restrict__ p = x + (size_t)row * L4;
                    float s = 0.0f;
                    #pragma unroll
                    for (int i = 0; i < ITER; ++i) {
                        float4 v = __ldg(p + t + i * 256);
                        s += (v.x + v.y) + (v.z + v.w);
                    }
                    #pragma unroll
                    for (int off = 16; off > 0; off >>= 1)
                        s += __shfl_xor_sync(0xFFFFFFFFu, s, off);
                    if (lane == 0) warp_sums[wid] = s;
                    __syncthreads();
                    if (wid == 0) {
                        float tt = (lane < 8) ? warp_sums[lane] : 0.0f;
                        #pragma unroll
                        for (int off = 4; off > 0; off >>= 1)
                            tt += __shfl_xor_sync(0xFFFFFFFFu, tt, off);
                        if (lane == 0) {
                            d_y[row] = tt * (1.0f / (float)L_);
                            __threadfence();                 // release d_y
                            atomicAdd(&g_cnt[b], 1);
                        }
                    }
                } else {
                    // ---- EXCITE for batch b ----
                    if (t == 0) {
                        while (((volatile int*)g_cnt)[b] < C_) __nanosleep(32);
                    }
                    __syncthreads();
                    __threadfence();                         // acquire
                    ys[t] = __ldcg(&d_y[b * C_ + t]);
                    __syncthreads();
                    {
                        const int hh = t >> 4;
                        const int k  = t & 15;
                        const float* __restrict__ w1 = W1 + hh * C_ + k * 16;
                        const float* __restrict__ yy = ys + k * 16;
                        float s = 0.0f;
                        #pragma unroll
                        for (int i = 0; i < 16; ++i) s += yy[i] * w1[i];
                        #pragma unroll
                        for (int off = 8; off > 0; off >>= 1)
                            s += __shfl_down_sync(0xFFFFFFFFu, s, off, 16);
                        if (k == 0) hs[hh] = fmaxf(s, 0.0f);
                    }
                    __syncthreads();
                    {
                        float s = 0.0f;
                        const float* __restrict__ w2 = W2 + t * H_;
                        #pragma unroll
                        for (int j = 0; j < H_; ++j) s += hs[j] * w2[j];
                        d_g[b * C_ + t] = 1.0f / (1.0f + expf(-s));
                    }
                    __threadfence();                         // release d_g
                    __syncthreads();
                    if (t == 0) atomicExch(&g_flag[b], 1);
                }
            } else {
                // ---- SCALE row: __ldcs (L2 hit expected) * gate -> __stcs ----
                const int row = scale_idx;
                const int b   = row >> 8;
                if (t == 0) {
                    while (((volatile int*)g_flag)[b] == 0) __nanosleep(32);
                }
                __syncthreads();
                __threadfence();                             // acquire
                const float gv = __ldcg(&d_g[row]);

                const float4* __restrict__ px = x   + (size_t)row * L4 + t;
                float4* __restrict__       po = out + (size_t)row * L4 + t;
                #pragma unroll
                for (int g2 = 0; g2 < 2; ++g2) {
                    float4 v[4];
                    #pragma unroll
                    for (int i = 0; i < 4; ++i)
                        v[i] = __ldcs(px + (g2 * 4 + i) * 256);
                    #pragma unroll
                    for (int i = 0; i < 4; ++i) {
                        v[i].x *= gv; v[i].y *= gv; v[i].z *= gv; v[i].w *= gv;
                        __stcs(po + (g2 * 4 + i) * 256, v[i]);
                    }
                }
            }
            __syncthreads();   // smem reuse safety between subtasks / grabs
        }
    }
}

// ---------------------------------------------------------------------------
extern "C" void kernel_launch(void* const* d_in, const int* in_sizes, int n_in,
                              void* d_out, int out_size) {
    const float4* x  = (const float4*)d_in[0];
    const float*  W1 = (const float*)d_in[1];
    const float*  W2 = (const float*)d_in[2];
    float4* out = (float4*)d_out;

    se_init<<<1, 64>>>();
    se_persist<<<P_BLOCKS, TPB>>>(x, out, W1, W2);
}

// round 14
// speedup vs baseline: 1.5992x; 1.5992x over previous
#include <cuda_runtime.h>
#include <math.h>

// Problem constants
#define B_    32
#define C_    256
#define L_    8192
#define H_    16
#define ROWS  (B_ * C_)          // 8192
#define L4    (L_ / 4)           // 2048 float4 per row
#define ITER  8
#define TPB   256

// 1-row tasks (R7 geometry — proven traffic floor ~494MB).
// mean-stream: per batch [256 means, 1 excite] = 8224; scale-stream: 8192.
#define NM    (B_ * (C_ + 1))    // 8224
#define NS    ROWS               // 8192
#define NTASKS (NM + NS)         // 16416
// Prefetch => 2 tasks in flight per block => completion frontier = 1776.
// gap(excite->scale) = 2*LEAD - 513 - 2b. LEAD=1600 -> gap ~2687, margin ~900.
#define LEAD  1600
#define ALT_END (LEAD + 2 * (NM - LEAD))   // 14848
#define P_BLOCKS 888

// Scratch (allocation-free rule: __device__ globals)
__device__ float d_y[ROWS];
__device__ float d_g[ROWS];
__device__ int   g_task;
__device__ int   g_cnt[B_];
__device__ int   g_flag[B_];

// ---------------------------------------------------------------------------
__global__ void se_init() {
    const int t = threadIdx.x;
    if (t == 0) g_task = 0;
    if (t < B_) { g_cnt[t] = 0; g_flag[t] = 0; }
}

// ---------------------------------------------------------------------------
// Persistent worker. Dynamic in-order queue with ONE-deep task-id prefetch:
// thread 0 grabs task k+1 at the start of task k, so the dispatch atomic's
// latency overlaps task k's memory work. In-flight = 2 tasks/block, so the
// ordering frontier is 1776 positions — LEAD=1600 keeps every flag/cnt
// dependency ~900 positions clear of it (R8 failed with margin -233,
// R12 with +49; R7 succeeded with +655).
// ---------------------------------------------------------------------------
__global__ __launch_bounds__(TPB, 6) void se_persist(const float4* __restrict__ x,
                                                     float4* __restrict__ out,
                                                     const float* __restrict__ W1,
                                                     const float* __restrict__ W2) {
    __shared__ int   s_task[2];
    __shared__ float warp_sums[8];
    __shared__ float ys[C_];
    __shared__ float hs[H_];

    const int t    = threadIdx.x;
    const int lane = t & 31;
    const int wid  = t >> 5;

    if (t == 0) s_task[0] = atomicAdd(&g_task, 1);
    __syncthreads();

    int parity = 0;
    for (;;) {
        const int task = s_task[parity];
        if (task >= NTASKS) return;
        if (t == 0) s_task[parity ^ 1] = atomicAdd(&g_task, 1);  // prefetch next

        // ---- queue position -> (stream, index) ----
        int mean_idx = -1, scale_idx = -1;
        if (task < LEAD) {
            mean_idx = task;
        } else if (task < ALT_END) {
            const int j = task - LEAD;
            if (j & 1) mean_idx = LEAD + (j >> 1);
            else       scale_idx = j >> 1;
        } else {
            scale_idx = (NM - LEAD) + (task - ALT_END);
        }

        if (mean_idx >= 0) {
            const int b = mean_idx / (C_ + 1);
            const int r = mean_idx - b * (C_ + 1);
            if (r < C_) {
                // ---- MEAN of row (b, r): default policy -> L2 resident ----
                const int row = b * C_ + r;
                const float4* __restrict__ p = x + (size_t)row * L4;
                float s = 0.0f;
                #pragma unroll
                for (int i = 0; i < ITER; ++i) {
                    float4 v = __ldg(p + t + i * 256);
                    s += (v.x + v.y) + (v.z + v.w);
                }
                #pragma unroll
                for (int off = 16; off > 0; off >>= 1)
                    s += __shfl_xor_sync(0xFFFFFFFFu, s, off);
                if (lane == 0) warp_sums[wid] = s;
                __syncthreads();
                if (wid == 0) {
                    float tt = (lane < 8) ? warp_sums[lane] : 0.0f;
                    #pragma unroll
                    for (int off = 4; off > 0; off >>= 1)
                        tt += __shfl_xor_sync(0xFFFFFFFFu, tt, off);
                    if (lane == 0) {
                        d_y[row] = tt * (1.0f / (float)L_);
                        __threadfence();                    // release d_y
                        atomicAdd(&g_cnt[b], 1);
                    }
                }
            } else {
                // ---- EXCITE for batch b (waits only on trailing means) ----
                if (t == 0) {
                    while (((volatile int*)g_cnt)[b] < C_) __nanosleep(32);
                }
                __syncthreads();
                __threadfence();                            // acquire
                ys[t] = __ldcg(&d_y[b * C_ + t]);
                __syncthreads();
                {
                    const int hh = t >> 4;
                    const int k  = t & 15;
                    const float* __restrict__ w1 = W1 + hh * C_ + k * 16;
                    const float* __restrict__ yy = ys + k * 16;
                    float s = 0.0f;
                    #pragma unroll
                    for (int i = 0; i < 16; ++i) s += yy[i] * w1[i];
                    #pragma unroll
                    for (int off = 8; off > 0; off >>= 1)
                        s += __shfl_down_sync(0xFFFFFFFFu, s, off, 16);
                    if (k == 0) hs[hh] = fmaxf(s, 0.0f);
                }
                __syncthreads();
                {
                    float s = 0.0f;
                    const float* __restrict__ w2 = W2 + t * H_;
                    #pragma unroll
                    for (int j = 0; j < H_; ++j) s += hs[j] * w2[j];
                    d_g[b * C_ + t] = 1.0f / (1.0f + expf(-s));
                }
                __threadfence();                            // release d_g
                __syncthreads();
                if (t == 0) atomicExch(&g_flag[b], 1);
            }
        } else {
            // ---- SCALE row: __ldcs (L2 hit expected) * gate -> __stcs ----
            const int row = scale_idx;
            const int b   = row >> 8;
            if (t == 0) {
                while (((volatile int*)g_flag)[b] == 0) __nanosleep(32);
            }
            __syncthreads();
            __threadfence();                                // acquire
            const float gv = __ldcg(&d_g[row]);

            const float4* __restrict__ px = x   + (size_t)row * L4 + t;
            float4* __restrict__       po = out + (size_t)row * L4 + t;
            #pragma unroll
            for (int g2 = 0; g2 < 2; ++g2) {
                float4 v[4];
                #pragma unroll
                for (int i = 0; i < 4; ++i)
                    v[i] = __ldcs(px + (g2 * 4 + i) * 256);
                #pragma unroll
                for (int i = 0; i < 4; ++i) {
                    v[i].x *= gv; v[i].y *= gv; v[i].z *= gv; v[i].w *= gv;
                    __stcs(po + (g2 * 4 + i) * 256, v[i]);
                }
            }
        }
        __syncthreads();   // smem reuse + prefetched id visibility
        parity ^= 1;
    }
}

// ---------------------------------------------------------------------------
extern "C" void kernel_launch(void* const* d_in, const int* in_sizes, int n_in,
                              void* d_out, int out_size) {
    const float4* x  = (const float4*)d_in[0];
    const float*  W1 = (const float*)d_in[1];
    const float*  W2 = (const float*)d_in[2];
    float4* out = (float4*)d_out;

    se_init<<<1, 64>>>();
    se_persist<<<P_BLOCKS, TPB>>>(x, out, W1, W2);
}